// round 15
// baseline (speedup 1.0000x reference)
#include <cuda_runtime.h>
#include <math.h>

// ---------------- problem constants ----------------
#define TN    131072     // local tx nodes
#define ELN   524288     // local edges
#define NNODE 50000      // global contract nodes
#define EGN   400000     // global edges
#define BB    8192       // batch of contracts
#define HH    128        // hidden dim
#define FGN   7          // global feat dim
#define HCN   64         // classifier hidden
#define CC    2          // classes
#define CATP  144        // padded concat row stride (16B multiple)

#define CDIV(a,b) (((a)+(b)-1)/(b))
#define NBL  CDIV(TN, 1024)
#define NBG  CDIV(NNODE, 1024)

// pre-rounded weight buffer offsets (floats)
#define WT_LOC0 0
#define WT_LOC1 16384
#define WT_FP   32768
#define WT_G0   50048
#define WT_G1   66432
#define WT_TOT  82816

// ---------------- scratch (device globals) ----------------
__device__ float g_h   [TN*HH];
__device__ float g_z   [TN*HH];
__device__ float g_ssrc[TN*4];
__device__ float g_sdst[TN*4];
__device__ float g_cat [BB*CATP];
__device__ float g_tmp [BB*HH];
__device__ float g_gx  [NNODE*HH];
__device__ float g_gz  [NNODE*HH];
__device__ float g_wtf [WT_TOT];
// CSR scratch
__device__ int   g_deg   [TN];
__device__ int   g_rowptr[TN+1];
__device__ int   g_fill  [TN];
__device__ int   g_psrc  [ELN];
__device__ float g_pea   [ELN];
__device__ int   g_bsum  [256];
__device__ int   g_gdeg   [NNODE];
__device__ int   g_growptr[NNODE+1];
__device__ int   g_gfill  [NNODE];
__device__ int   g_gpsrc  [EGN];
__device__ int   g_gbsum  [256];

// ---------------- helpers ----------------
__device__ __forceinline__ unsigned f2tf32(float f) {
    unsigned r;
    asm("cvt.rna.tf32.f32 %0, %1;" : "=r"(r) : "f"(f));
    return r;
}
__device__ __forceinline__ void cp_async16(unsigned dst, const void* src, int bytes) {
    asm volatile("cp.async.cg.shared.global [%0], [%1], 16, %2;"
                 :: "r"(dst), "l"(src), "r"(bytes) : "memory");
}
__device__ __forceinline__ void cp_commit() {
    asm volatile("cp.async.commit_group;" ::: "memory");
}
__device__ __forceinline__ void cp_wait0() {
    asm volatile("cp.async.wait_group 0;" ::: "memory");
}

// ---------------- weight pre-rounding + deg zeroing ----------
__global__ void wconv_k(const float* __restrict__ locW, const float* __restrict__ fpW,
                        const float* __restrict__ globW, float* __restrict__ wt,
                        int* __restrict__ deg, int* __restrict__ gdeg) {
    int i = blockIdx.x * blockDim.x + threadIdx.x;
    if (i < 32768)       wt[i] = __uint_as_float(f2tf32(locW[i]));
    else if (i < 50048)  wt[i] = __uint_as_float(f2tf32(fpW[i - 32768]));
    else if (i < WT_TOT) wt[i] = __uint_as_float(f2tf32(globW[i - 50048]));
    if (i < TN)    deg[i]  = 0;
    if (i < NNODE) gdeg[i] = 0;
}

// ================= CSR construction (both graphs fused) =================
__global__ void hist2_k(const int* __restrict__ ldst, const int* __restrict__ gdst,
                        int* __restrict__ deg, int* __restrict__ gdeg) {
    int e = blockIdx.x * blockDim.x + threadIdx.x;
    if (e < ELN) atomicAdd(&deg[ldst[e]], 1);
    else if (e < ELN + EGN) atomicAdd(&gdeg[gdst[e - ELN]], 1);
}
__global__ void scan1b_k(const int* __restrict__ deg, const int* __restrict__ gdeg,
                         int* __restrict__ bsum, int* __restrict__ gbsum) {
    __shared__ int s[256];
    int t = threadIdx.x;
    bool loc = blockIdx.x < NBL;
    const int* d = loc ? deg : gdeg;
    int n = loc ? TN : NNODE;
    int base = (loc ? blockIdx.x : blockIdx.x - NBL) * 1024;
    int sum = 0;
#pragma unroll
    for (int i = 0; i < 4; i++) {
        int idx = base + t * 4 + i;
        if (idx < n) sum += d[idx];
    }
    s[t] = sum; __syncthreads();
    for (int o = 128; o > 0; o >>= 1) { if (t < o) s[t] += s[t + o]; __syncthreads(); }
    if (t == 0) (loc ? bsum : gbsum)[loc ? blockIdx.x : blockIdx.x - NBL] = s[0];
}
__global__ void scan2b_k(int* __restrict__ bsum, int* __restrict__ gbsum,
                         int* __restrict__ rowptr, int* __restrict__ growptr) {
    if (threadIdx.x == 0) {
        int acc = 0;
        for (int i = 0; i < NBL; i++) { int v = bsum[i]; bsum[i] = acc; acc += v; }
        rowptr[TN] = ELN;
    } else if (threadIdx.x == 1) {
        int acc = 0;
        for (int i = 0; i < NBG; i++) { int v = gbsum[i]; gbsum[i] = acc; acc += v; }
        growptr[NNODE] = EGN;
    }
}
__global__ void scan3b_k(const int* __restrict__ deg, const int* __restrict__ gdeg,
                         const int* __restrict__ bsum, const int* __restrict__ gbsum,
                         int* __restrict__ rowptr, int* __restrict__ growptr,
                         int* __restrict__ fill, int* __restrict__ gfill) {
    __shared__ int s[256];
    int t = threadIdx.x;
    bool loc = blockIdx.x < NBL;
    const int* d = loc ? deg : gdeg;
    const int* bs = loc ? bsum : gbsum;
    int* rp = loc ? rowptr : growptr;
    int* fl = loc ? fill : gfill;
    int n = loc ? TN : NNODE;
    int bid = loc ? blockIdx.x : blockIdx.x - NBL;
    int base = bid * 1024;
    int v[4]; int sum = 0;
#pragma unroll
    for (int i = 0; i < 4; i++) {
        int idx = base + t * 4 + i;
        v[i] = (idx < n) ? d[idx] : 0;
        sum += v[i];
    }
    s[t] = sum; __syncthreads();
    for (int o = 1; o < 256; o <<= 1) {
        int x = (t >= o) ? s[t - o] : 0;
        __syncthreads();
        s[t] += x;
        __syncthreads();
    }
    int excl = ((t == 0) ? 0 : s[t - 1]) + bs[bid];
#pragma unroll
    for (int i = 0; i < 4; i++) {
        int idx = base + t * 4 + i;
        if (idx < n) { rp[idx] = excl; fl[idx] = excl; }
        excl += v[i];
    }
}
__global__ void scatedge2_k(const int* __restrict__ lsrc, const int* __restrict__ ldst,
                            const int* __restrict__ gsrc, const int* __restrict__ gdst,
                            const float* __restrict__ eattr,
                            int* __restrict__ fill, int* __restrict__ gfill,
                            int* __restrict__ psrc, float* __restrict__ pea,
                            int* __restrict__ gpsrc) {
    int e = blockIdx.x * blockDim.x + threadIdx.x;
    if (e < ELN) {
        int p = atomicAdd(&fill[ldst[e]], 1);
        psrc[p] = lsrc[e];
        pea[p] = eattr[e];
    } else if (e < ELN + EGN) {
        int ee = e - ELN;
        int p = atomicAdd(&gfill[gdst[ee]], 1);
        gpsrc[p] = gsrc[ee];
    }
}

// ================= tf32 MMA GEMM: BM=128, BK=32, cp.async pipeline ===============
// IP=true: compute h-tile = x@Win+bin in the prologue, write DIRECTLY into the
// 4 A stage-slices in smem (K=128) + hout for later use; mainloop then streams
// W only (no A loads, no fence). IP=false: standard 2-stage A+W pipeline.
#define APAD 36
#define WPAD 136
#define ABUF (128 * APAD)
#define WBUF (32 * WPAD)
#define SMEM_MMA   ((2 * ABUF + 2 * WBUF) * 4)   // 71680 B (non-IP)
#define SMEM_MMAIP ((4 * ABUF + 2 * WBUF) * 4)   // 108544 B (IP)
template <int NH, bool IP>
__global__ __launch_bounds__(256, 2)
void gemm_mma(const float* __restrict__ A, const float* __restrict__ W,
              const float* __restrict__ bias, float* __restrict__ C,
              int M, int K, int lda,
              const float* __restrict__ asrc, const float* __restrict__ adst,
              float* __restrict__ ssrc, float* __restrict__ sdst,
              const float* __restrict__ x, const float* __restrict__ Win,
              const float* __restrict__ binp, float* __restrict__ hout) {
    extern __shared__ __align__(16) float smem[];
    float* As = smem;                                   // IP: 4 slices, else 2
    float* Ws = smem + (IP ? 4 : 2) * ABUF;
    const int tid  = threadIdx.x;
    const int warp = tid >> 5, lane = tid & 31;
    const int bm   = blockIdx.x * 128;
    const int wm   = (warp >> 1) * 32;
    const int wn   = (warp & 1) * 64;
    const int g    = lane >> 2;
    const int ct   = lane & 3;
    const int nk   = (K + 31) / 32;

    if (IP) {
        // input projection prologue: h_tile = x_tile(128x4) @ Win(4x128) + bin
        // written straight into the 4 A stage-slices + hout (for graph reuse).
        float* xs   = Ws;         // reuse W region as temp: 512 floats
        float* WinS = Ws + 512;   // 512 floats
        float* binS = Ws + 1024;  // 128 floats
        for (int i = tid; i < 512; i += 256) {
            int m = i >> 2, j = i & 3;
            int gr = bm + m;
            xs[i] = (gr < M) ? x[(size_t)gr * 4 + j] : 0.f;
            WinS[i] = Win[i];
        }
        if (tid < 128) binS[tid] = binp[tid];
        __syncthreads();
        for (int i = tid; i < 128 * 128; i += 256) {
            int m = i >> 7, k = i & 127;
            float v = binS[k]
                    + xs[m * 4 + 0] * WinS[k]
                    + xs[m * 4 + 1] * WinS[128 + k]
                    + xs[m * 4 + 2] * WinS[256 + k]
                    + xs[m * 4 + 3] * WinS[384 + k];
            As[(k >> 5) * ABUF + m * APAD + (k & 31)] = v;
            int gr = bm + m;
            if (gr < M) hout[(size_t)gr * 128 + k] = v;
        }
        __syncthreads();   // As ready; Ws temp region will be overwritten by loader
    }

    const unsigned asb = (unsigned)__cvta_generic_to_shared(As);
    const unsigned wsb = (unsigned)__cvta_generic_to_shared(Ws);

    float c[2][8][4];
#pragma unroll
    for (int mt = 0; mt < 2; mt++)
#pragma unroll
        for (int nt = 0; nt < 8; nt++)
#pragma unroll
            for (int r = 0; r < 4; r++) c[mt][nt][r] = 0.f;

    auto issue = [&](int buf, int t) {
        int k0 = t * 32;
        if (!IP) {
#pragma unroll
            for (int j = 0; j < 4; j++) {
                int id = tid + 256 * j;
                int m = id >> 3, kq = (id & 7) * 4;
                int gr = bm + m, gk = k0 + kq;
                int bytes = 0;
                const float* src = A;
                if (gr < M && gk < K) {
                    int rem = K - gk;
                    bytes = rem >= 4 ? 16 : rem * 4;
                    src = A + (size_t)gr * lda + gk;
                }
                cp_async16(asb + (unsigned)(buf * ABUF + m * APAD + kq) * 4u, src, bytes);
            }
        }
#pragma unroll
        for (int j = 0; j < 4; j++) {
            int id = tid + 256 * j;
            int k = id >> 5, nq = (id & 31) * 4;
            int gk = k0 + k;
            int bytes = (gk < K) ? 16 : 0;
            const float* src = (gk < K) ? (W + (size_t)gk * 128 + nq) : W;
            cp_async16(wsb + (unsigned)(buf * WBUF + k * WPAD + nq) * 4u, src, bytes);
        }
        cp_commit();
    };

    issue(0, 0);

    for (int t = 0; t < nk; t++) {
        cp_wait0();
        __syncthreads();
        if (t + 1 < nk) issue((t + 1) & 1, t + 1);

        const float* Ab = As + (IP ? t : (t & 1)) * ABUF;
        const unsigned* Wb = (const unsigned*)(Ws + (t & 1) * WBUF);
#pragma unroll
        for (int ks = 0; ks < 32; ks += 8) {
            unsigned b[8][2];
#pragma unroll
            for (int nt = 0; nt < 8; nt++) {
                int n = wn + nt * 8 + g;
                b[nt][0] = Wb[(ks + ct) * WPAD + n];
                b[nt][1] = Wb[(ks + ct + 4) * WPAD + n];
            }
#pragma unroll
            for (int mt = 0; mt < 2; mt++) {
                int r0 = wm + mt * 16 + g;
                unsigned a0 = f2tf32(Ab[r0 * APAD + ks + ct]);
                unsigned a1 = f2tf32(Ab[(r0 + 8) * APAD + ks + ct]);
                unsigned a2 = f2tf32(Ab[r0 * APAD + ks + ct + 4]);
                unsigned a3 = f2tf32(Ab[(r0 + 8) * APAD + ks + ct + 4]);
#pragma unroll
                for (int nt = 0; nt < 8; nt++) {
                    asm volatile(
                        "mma.sync.aligned.m16n8k8.row.col.f32.tf32.tf32.f32 "
                        "{%0,%1,%2,%3}, {%4,%5,%6,%7}, {%8,%9}, {%0,%1,%2,%3};"
                        : "+f"(c[mt][nt][0]), "+f"(c[mt][nt][1]),
                          "+f"(c[mt][nt][2]), "+f"(c[mt][nt][3])
                        : "r"(a0), "r"(a1), "r"(a2), "r"(a3),
                          "r"(b[nt][0]), "r"(b[nt][1]));
                }
            }
        }
        __syncthreads();
    }

    // epilogue: store C (+bias) and optionally fused attention scores
    const int NH2 = (NH == 4) ? 2 : 1;
    float ps[2][2][2], pd[2][2][2];
    if (NH > 0) {
#pragma unroll
        for (int a = 0; a < 2; a++)
#pragma unroll
            for (int b2 = 0; b2 < 2; b2++)
#pragma unroll
                for (int d = 0; d < 2; d++) { ps[a][b2][d] = 0.f; pd[a][b2][d] = 0.f; }
    }
#pragma unroll
    for (int mt = 0; mt < 2; mt++) {
        int row0 = bm + wm + mt * 16 + g;
        int row1 = row0 + 8;
#pragma unroll
        for (int nt = 0; nt < 8; nt++) {
            int col = wn + nt * 8 + 2 * ct;
            float b0 = bias ? bias[col] : 0.f;
            float b1 = bias ? bias[col + 1] : 0.f;
            float v00 = c[mt][nt][0] + b0, v01 = c[mt][nt][1] + b1;
            float v10 = c[mt][nt][2] + b0, v11 = c[mt][nt][3] + b1;
            if (row0 < M) *(float2*)(C + (size_t)row0 * 128 + col) = make_float2(v00, v01);
            if (row1 < M) *(float2*)(C + (size_t)row1 * 128 + col) = make_float2(v10, v11);
            if (NH > 0) {
                float a0s = asrc[col], a1s = asrc[col + 1];
                float a0d = adst[col], a1d = adst[col + 1];
                int h2 = (NH == 4) ? (nt >> 2) : 0;
                ps[mt][0][h2] += v00 * a0s + v01 * a1s;
                ps[mt][1][h2] += v10 * a0s + v11 * a1s;
                pd[mt][0][h2] += v00 * a0d + v01 * a1d;
                pd[mt][1][h2] += v10 * a0d + v11 * a1d;
            }
        }
    }
    if (NH > 0) {
#pragma unroll
        for (int mt = 0; mt < 2; mt++)
#pragma unroll
            for (int rh = 0; rh < 2; rh++)
#pragma unroll
                for (int h2 = 0; h2 < NH2; h2++) {
                    float s = ps[mt][rh][h2], d = pd[mt][rh][h2];
                    s += __shfl_xor_sync(0xffffffffu, s, 1);
                    s += __shfl_xor_sync(0xffffffffu, s, 2);
                    d += __shfl_xor_sync(0xffffffffu, d, 1);
                    d += __shfl_xor_sync(0xffffffffu, d, 2);
                    ps[mt][rh][h2] = s; pd[mt][rh][h2] = d;
                }
        if (ct == 0) {
            int headbase = (wn * NH) >> 7;
#pragma unroll
            for (int mt = 0; mt < 2; mt++)
#pragma unroll
                for (int rh = 0; rh < 2; rh++) {
                    int row = bm + wm + mt * 16 + g + rh * 8;
                    if (row < M) {
#pragma unroll
                        for (int h2 = 0; h2 < NH2; h2++) {
                            int head = headbase + h2;
                            ssrc[(size_t)row * NH + head] = ps[mt][rh][h2];
                            sdst[(size_t)row * NH + head] = pd[mt][rh][h2];
                        }
                    }
                }
        }
    }
}

// ---------------- SIMT GEMM for tiny-K projections (+optional fused LN+ReLU) --------
__global__ __launch_bounds__(256, 2)
void gemm_tile(const float* __restrict__ A, const float* __restrict__ W,
               const float* __restrict__ bias, float* __restrict__ C,
               int M, int K,
               const float* __restrict__ gamma, const float* __restrict__ beta) {
    __shared__ float As[16 * 132];
    __shared__ float Ws[16 * 132];
    const int bm  = blockIdx.x * 128;
    const int tid = threadIdx.x;
    const int tr  = (tid >> 4) * 8;
    const int tc  = (tid & 15) * 8;
    float acc[8][8];
#pragma unroll
    for (int x = 0; x < 8; x++)
#pragma unroll
        for (int y = 0; y < 8; y++) acc[x][y] = 0.f;

    for (int k0 = 0; k0 < K; k0 += 16) {
        for (int i = tid; i < 128 * 16; i += 256) {
            int m = i >> 4, kk = i & 15;
            int gr = bm + m, gk = k0 + kk;
            As[kk * 132 + m] = (gr < M && gk < K) ? A[(size_t)gr * K + gk] : 0.f;
        }
        for (int i = tid; i < 16 * 128; i += 256) {
            int kk = i >> 7, n = i & 127;
            int gk = k0 + kk;
            Ws[kk * 132 + n] = (gk < K) ? W[gk * 128 + n] : 0.f;
        }
        __syncthreads();
#pragma unroll
        for (int kk = 0; kk < 16; kk++) {
            float a[8], w[8];
#pragma unroll
            for (int x = 0; x < 8; x++) a[x] = As[kk * 132 + tr + x];
#pragma unroll
            for (int y = 0; y < 8; y++) w[y] = Ws[kk * 132 + tc + y];
#pragma unroll
            for (int x = 0; x < 8; x++)
#pragma unroll
                for (int y = 0; y < 8; y++) acc[x][y] += a[x] * w[y];
        }
        __syncthreads();
    }

    if (gamma) {
#pragma unroll
        for (int x = 0; x < 8; x++) {
            int gr = bm + tr + x;
            float vv[8]; float sum = 0.f;
#pragma unroll
            for (int y = 0; y < 8; y++) {
                vv[y] = acc[x][y] + (bias ? bias[tc + y] : 0.f);
                sum += vv[y];
            }
#pragma unroll
            for (int k = 1; k < 16; k <<= 1) sum += __shfl_xor_sync(0xffffffffu, sum, k, 16);
            float mean = sum * (1.f / 128.f);
            float sq = 0.f;
#pragma unroll
            for (int y = 0; y < 8; y++) { float d = vv[y] - mean; sq += d * d; }
#pragma unroll
            for (int k = 1; k < 16; k <<= 1) sq += __shfl_xor_sync(0xffffffffu, sq, k, 16);
            float rstd = rsqrtf(sq * (1.f / 128.f) + 1e-5f);
            if (gr < M) {
#pragma unroll
                for (int y = 0; y < 8; y++) {
                    float yv = (vv[y] - mean) * rstd * gamma[tc + y] + beta[tc + y];
                    C[(size_t)gr * 128 + tc + y] = fmaxf(yv, 0.f);
                }
            }
        }
    } else {
#pragma unroll
        for (int x = 0; x < 8; x++) {
            int gr = bm + tr + x;
            if (gr < M) {
#pragma unroll
                for (int y = 0; y < 8; y++) {
                    float v = acc[x][y];
                    if (bias) v += bias[tc + y];
                    C[(size_t)gr * 128 + tc + y] = v;
                }
            }
        }
    }
}

// ---------------- fused single-pass GAT aggregation ----------------
template <int NH, int HD, bool HAS_E>
__global__ void gat_fused(const int* __restrict__ rowptr, const int* __restrict__ psrc,
                          const float* __restrict__ pea,
                          const float* __restrict__ eW, const float* __restrict__ ae,
                          const float* __restrict__ ssrc, const float* __restrict__ sdst,
                          const float* __restrict__ z, const float* __restrict__ bias,
                          float* __restrict__ h, int n) {
    __shared__ float ce_s[NH];
    if (HAS_E && threadIdx.x < NH) {
        int hh = threadIdx.x;
        float s = 0.f;
#pragma unroll
        for (int d = 0; d < HD; d++) s += eW[hh * HD + d] * ae[hh * HD + d];
        ce_s[hh] = s;
    }
    if (HAS_E) __syncthreads();

    int node = blockIdx.x * 8 + (threadIdx.x >> 5);
    if (node >= n) return;
    int lane = threadIdx.x & 31;
    int c = lane * 4;
    int head = c / HD;

    float sd = sdst[(size_t)node * NH + head];
    float ce = HAS_E ? ce_s[head] : 0.f;

    float4 acc = make_float4(0.f, 0.f, 0.f, 0.f);
    float den = 0.f;
    int lo = rowptr[node], hi = rowptr[node + 1];
    for (int j = lo; j < hi; j++) {
        int s = psrc[j];
        float sc = ssrc[(size_t)s * NH + head] + sd;
        if (HAS_E) sc += pea[j] * ce;
        sc = sc > 0.f ? sc : 0.2f * sc;
        float ex = __expf(sc);
        den += ex;
        float4 zv = *(const float4*)(z + (size_t)s * HH + c);
        acc.x += ex * zv.x; acc.y += ex * zv.y;
        acc.z += ex * zv.z; acc.w += ex * zv.w;
    }
    float inv = 1.f / fmaxf(den, 1e-16f);
    float4 hv = *(const float4*)(h + (size_t)node * HH + c);
    float4 bv = *(const float4*)(bias + c);
    acc.x = hv.x + bv.x + acc.x * inv;
    acc.y = hv.y + bv.y + acc.y * inv;
    acc.z = hv.z + bv.z + acc.z * inv;
    acc.w = hv.w + bv.w + acc.w * inv;
    acc.x = acc.x > 0.f ? acc.x : __expf(acc.x) - 1.f;
    acc.y = acc.y > 0.f ? acc.y : __expf(acc.y) - 1.f;
    acc.z = acc.z > 0.f ? acc.z : __expf(acc.z) - 1.f;
    acc.w = acc.w > 0.f ? acc.w : __expf(acc.w) - 1.f;
    *(float4*)(h + (size_t)node * HH + c) = acc;
}

// ---------------- pooling -> padded cat rows (+ gfeat tail) ----------------
__global__ void pool_cat_k(const float* __restrict__ h, const int* __restrict__ nb,
                           const float* __restrict__ gf, const int* __restrict__ cid,
                           float* __restrict__ cat) {
    int b = blockIdx.x, t = threadIdx.x;
    int lo = 0, hi = TN;
    while (lo < hi) { int mid = (lo + hi) >> 1; if (nb[mid] < b) lo = mid + 1; else hi = mid; }
    int start = lo;
    hi = TN;
    while (lo < hi) { int mid = (lo + hi) >> 1; if (nb[mid] < b + 1) lo = mid + 1; else hi = mid; }
    int end = lo;
    float s = 0.f;
    for (int i = start; i < end; i++) s += h[(size_t)i * HH + t];
    cat[(size_t)b * CATP + t] = s / fmaxf((float)(end - start), 1.f);
    if (t < FGN)
        cat[(size_t)b * CATP + HH + t] = gf[(size_t)cid[b] * FGN + t];
}

// ---------------- LayerNorm(128) + ReLU, scattered to gx[cid] ----------------
__global__ void ln_relu_scat_k(const float* __restrict__ X, const float* __restrict__ g,
                               const float* __restrict__ be, const int* __restrict__ cid,
                               float* __restrict__ gx) {
    int row = blockIdx.x, t = threadIdx.x;
    float v = X[(size_t)row * HH + t];
    __shared__ float red[HH];
    red[t] = v; __syncthreads();
    for (int s = 64; s > 0; s >>= 1) { if (t < s) red[t] += red[t + s]; __syncthreads(); }
    float mean = red[0] / 128.f;
    __syncthreads();
    float dv = v - mean;
    red[t] = dv * dv; __syncthreads();
    for (int s = 64; s > 0; s >>= 1) { if (t < s) red[t] += red[t + s]; __syncthreads(); }
    float var = red[0] / 128.f;
    float y = dv * rsqrtf(var + 1e-5f) * g[t] + be[t];
    gx[(size_t)cid[row] * HH + t] = fmaxf(y, 0.f);
}

// ---------------- classifier: 8 contracts per block ----------------
__global__ __launch_bounds__(256)
void classifier_k(const float* __restrict__ gx, const int* __restrict__ cid,
                  const float* __restrict__ W1, const float* __restrict__ b1,
                  const float* __restrict__ W2, const float* __restrict__ b2,
                  float* __restrict__ out) {
    __shared__ float row[4][HH];
    __shared__ float hc[4][HCN];
    int tid = threadIdx.x;
    int grp = tid >> 6, t = tid & 63;
    for (int it = 0; it < 2; it++) {
        int b = blockIdx.x * 8 + it * 4 + grp;
        __syncthreads();
        const float* srcp = gx + (size_t)cid[b] * HH;
        row[grp][t] = srcp[t];
        row[grp][t + 64] = srcp[t + 64];
        __syncthreads();
        float s = b1[t];
#pragma unroll
        for (int k = 0; k < HH; k++) s += row[grp][k] * W1[k * HCN + t];
        hc[grp][t] = fmaxf(s, 0.f);
        __syncthreads();
        if (t < CC) {
            float s2 = b2[t];
#pragma unroll
            for (int k = 0; k < HCN; k++) s2 += hc[grp][k] * W2[k * CC + t];
            out[b * CC + t] = s2;
        }
    }
}

// ---------------- launch ----------------
extern "C" void kernel_launch(void* const* d_in, const int* in_sizes, int n_in,
                              void* d_out, int out_size) {
    const float* x_local    = (const float*)d_in[0];
    const float* eattr      = (const float*)d_in[1];
    const float* gfeat      = (const float*)d_in[2];
    const float* loc_in_W   = (const float*)d_in[3];
    const float* loc_in_b   = (const float*)d_in[4];
    const float* loc_W      = (const float*)d_in[5];
    const float* loc_asrc   = (const float*)d_in[6];
    const float* loc_adst   = (const float*)d_in[7];
    const float* loc_eW     = (const float*)d_in[8];
    const float* loc_ae     = (const float*)d_in[9];
    const float* loc_b      = (const float*)d_in[10];
    const float* fp_W       = (const float*)d_in[11];
    const float* fp_b       = (const float*)d_in[12];
    const float* fp_g       = (const float*)d_in[13];
    const float* fp_beta    = (const float*)d_in[14];
    const float* gp_W       = (const float*)d_in[15];
    const float* gp_b       = (const float*)d_in[16];
    const float* gp_g       = (const float*)d_in[17];
    const float* gp_beta    = (const float*)d_in[18];
    const float* glob_W     = (const float*)d_in[19];
    const float* glob_asrc  = (const float*)d_in[20];
    const float* glob_adst  = (const float*)d_in[21];
    const float* glob_b     = (const float*)d_in[22];
    const float* cls_W1     = (const float*)d_in[23];
    const float* cls_b1     = (const float*)d_in[24];
    const float* cls_W2     = (const float*)d_in[25];
    const float* cls_b2     = (const float*)d_in[26];
    const int*   eil        = (const int*)d_in[27];
    const int*   node_batch = (const int*)d_in[28];
    const int*   cid        = (const int*)d_in[29];
    const int*   gei        = (const int*)d_in[30];

    const int* lsrc = eil;
    const int* ldst = eil + ELN;
    const int* gsrc = gei;
    const int* gdst = gei + EGN;

    float *p_h, *p_z, *p_ssrc, *p_sdst;
    float *p_cat, *p_tmp, *p_gx, *p_gz, *p_pea, *p_wtf;
    int *p_deg, *p_rowptr, *p_fill, *p_psrc, *p_bsum;
    int *p_gdeg, *p_growptr, *p_gfill, *p_gpsrc, *p_gbsum;
    cudaGetSymbolAddress((void**)&p_h, g_h);
    cudaGetSymbolAddress((void**)&p_z, g_z);
    cudaGetSymbolAddress((void**)&p_ssrc, g_ssrc);
    cudaGetSymbolAddress((void**)&p_sdst, g_sdst);
    cudaGetSymbolAddress((void**)&p_cat, g_cat);
    cudaGetSymbolAddress((void**)&p_tmp, g_tmp);
    cudaGetSymbolAddress((void**)&p_gx, g_gx);
    cudaGetSymbolAddress((void**)&p_gz, g_gz);
    cudaGetSymbolAddress((void**)&p_pea, g_pea);
    cudaGetSymbolAddress((void**)&p_wtf, g_wtf);
    cudaGetSymbolAddress((void**)&p_deg, g_deg);
    cudaGetSymbolAddress((void**)&p_rowptr, g_rowptr);
    cudaGetSymbolAddress((void**)&p_fill, g_fill);
    cudaGetSymbolAddress((void**)&p_psrc, g_psrc);
    cudaGetSymbolAddress((void**)&p_bsum, g_bsum);
    cudaGetSymbolAddress((void**)&p_gdeg, g_gdeg);
    cudaGetSymbolAddress((void**)&p_growptr, g_growptr);
    cudaGetSymbolAddress((void**)&p_gfill, g_gfill);
    cudaGetSymbolAddress((void**)&p_gpsrc, g_gpsrc);
    cudaGetSymbolAddress((void**)&p_gbsum, g_gbsum);

    // dynamic smem opt-in
    cudaFuncSetAttribute((const void*)gemm_mma<4, true>,
                         cudaFuncAttributeMaxDynamicSharedMemorySize, SMEM_MMAIP);
    cudaFuncSetAttribute((const void*)gemm_mma<4, false>,
                         cudaFuncAttributeMaxDynamicSharedMemorySize, SMEM_MMA);
    cudaFuncSetAttribute((const void*)gemm_mma<2, false>,
                         cudaFuncAttributeMaxDynamicSharedMemorySize, SMEM_MMA);
    cudaFuncSetAttribute((const void*)gemm_mma<0, false>,
                         cudaFuncAttributeMaxDynamicSharedMemorySize, SMEM_MMA);

    // ---- weight pre-rounding + deg zeroing ----
    wconv_k<<<CDIV(TN, 256), 256>>>(loc_W, fp_W, glob_W, p_wtf, p_deg, p_gdeg);

    // ---- CSR hist (both graphs) ----
    hist2_k<<<CDIV(ELN + EGN, 256), 256>>>(ldst, gdst, p_deg, p_gdeg);
    scan1b_k<<<NBL + NBG, 256>>>(p_deg, p_gdeg, p_bsum, p_gbsum);

    // ---- local layer 0: fused IP + GEMM (+scores), A resident in smem — slot #4 ----
    gemm_mma<4, true><<<CDIV(TN, 128), 256, SMEM_MMAIP>>>(
        p_h, p_wtf + WT_LOC0, nullptr, p_z, TN, HH, HH,
        loc_asrc, loc_adst, p_ssrc, p_sdst,
        x_local, loc_in_W, loc_in_b, p_h);

    scan2b_k<<<1, 32>>>(p_bsum, p_gbsum, p_rowptr, p_growptr);
    scan3b_k<<<NBL + NBG, 256>>>(p_deg, p_gdeg, p_bsum, p_gbsum,
                                 p_rowptr, p_growptr, p_fill, p_gfill);
    scatedge2_k<<<CDIV(ELN + EGN, 256), 256>>>(lsrc, ldst, gsrc, gdst, eattr,
                                               p_fill, p_gfill, p_psrc, p_pea, p_gpsrc);

    // ---- local layer 0 aggregate ----
    gat_fused<4, 32, true><<<CDIV(TN, 8), 256>>>(p_rowptr, p_psrc, p_pea,
                                                 loc_eW, loc_ae,
                                                 p_ssrc, p_sdst, p_z, loc_b, p_h, TN);
    // ---- local layer 1 ----
    gemm_mma<4, false><<<CDIV(TN, 128), 256, SMEM_MMA>>>(
        p_h, p_wtf + WT_LOC1, nullptr, p_z, TN, HH, HH,
        loc_asrc + HH, loc_adst + HH, p_ssrc, p_sdst,
        nullptr, nullptr, nullptr, nullptr);
    gat_fused<4, 32, true><<<CDIV(TN, 8), 256>>>(p_rowptr, p_psrc, p_pea,
                                                 loc_eW + HH, loc_ae + HH,
                                                 p_ssrc, p_sdst, p_z, loc_b + HH, p_h, TN);

    // ---- pooling straight into padded cat rows ----
    pool_cat_k<<<BB, 128>>>(p_h, node_batch, gfeat, cid, p_cat);

    // ---- fused MLP ----
    gemm_mma<0, false><<<CDIV(BB, 128), 256, SMEM_MMA>>>(
        p_cat, p_wtf + WT_FP, fp_b, p_tmp, BB, HH + FGN, CATP,
        nullptr, nullptr, nullptr, nullptr,
        nullptr, nullptr, nullptr, nullptr);

    // ---- global projection (all N, fused LN+ReLU), then LN+scatter of fused rows ----
    gemm_tile<<<CDIV(NNODE, 128), 256>>>(gfeat, gp_W, gp_b, p_gx, NNODE, FGN,
                                         gp_g, gp_beta);
    ln_relu_scat_k<<<BB, HH>>>(p_tmp, fp_g, fp_beta, cid, p_gx);

    // ---- 2x global GATConv ----
    for (int l = 0; l < 2; l++) {
        gemm_mma<2, false><<<CDIV(NNODE, 128), 256, SMEM_MMA>>>(
            p_gx, p_wtf + (l == 0 ? WT_G0 : WT_G1), nullptr,
            p_gz, NNODE, HH, HH,
            glob_asrc + l * HH, glob_adst + l * HH, p_ssrc, p_sdst,
            nullptr, nullptr, nullptr, nullptr);
        gat_fused<2, 64, false><<<CDIV(NNODE, 8), 256>>>(p_growptr, p_gpsrc, (float*)nullptr,
                                                         (float*)nullptr, (float*)nullptr,
                                                         p_ssrc, p_sdst, p_gz,
                                                         glob_b + l * HH, p_gx, NNODE);
    }

    // ---- classifier ----
    classifier_k<<<CDIV(BB, 8), 256>>>(p_gx, cid, cls_W1, cls_b1, cls_W2, cls_b2,
                                       (float*)d_out);
}

// round 16
// speedup vs baseline: 1.0061x; 1.0061x over previous
#include <cuda_runtime.h>
#include <math.h>

// ---------------- problem constants ----------------
#define TN    131072     // local tx nodes
#define ELN   524288     // local edges
#define NNODE 50000      // global contract nodes
#define EGN   400000     // global edges
#define BB    8192       // batch of contracts
#define HH    128        // hidden dim
#define FGN   7          // global feat dim
#define HCN   64         // classifier hidden
#define CC    2          // classes
#define CATP  144        // padded concat row stride (16B multiple)

#define CDIV(a,b) (((a)+(b)-1)/(b))
#define NBL  CDIV(TN, 1024)
#define NBG  CDIV(NNODE, 1024)

// pre-rounded weight buffer offsets (floats)
#define WT_LOC0 0
#define WT_LOC1 16384
#define WT_FP   32768
#define WT_G0   50048
#define WT_G1   66432
#define WT_TOT  82816

// ---------------- scratch (device globals) ----------------
__device__ float g_h   [TN*HH];
__device__ float g_z   [TN*HH];
__device__ float g_ssrc[TN*4];
__device__ float g_sdst[TN*4];
__device__ float g_cat [BB*CATP];
__device__ float g_gx  [NNODE*HH];
__device__ float g_gz  [NNODE*HH];
__device__ float g_wtf [WT_TOT];
// CSR scratch
__device__ int   g_deg   [TN];
__device__ int   g_rowptr[TN+1];
__device__ int   g_fill  [TN];
__device__ int   g_psrc  [ELN];
__device__ float g_pea   [ELN];
__device__ int   g_bsum  [256];
__device__ int   g_gdeg   [NNODE];
__device__ int   g_growptr[NNODE+1];
__device__ int   g_gfill  [NNODE];
__device__ int   g_gpsrc  [EGN];
__device__ int   g_gbsum  [256];

// ---------------- helpers ----------------
__device__ __forceinline__ unsigned f2tf32(float f) {
    unsigned r;
    asm("cvt.rna.tf32.f32 %0, %1;" : "=r"(r) : "f"(f));
    return r;
}
__device__ __forceinline__ void cp_async16(unsigned dst, const void* src, int bytes) {
    asm volatile("cp.async.cg.shared.global [%0], [%1], 16, %2;"
                 :: "r"(dst), "l"(src), "r"(bytes) : "memory");
}
__device__ __forceinline__ void cp_commit() {
    asm volatile("cp.async.commit_group;" ::: "memory");
}
__device__ __forceinline__ void cp_wait0() {
    asm volatile("cp.async.wait_group 0;" ::: "memory");
}

// ---------------- weight pre-rounding + deg zeroing ----------
__global__ void wconv_k(const float* __restrict__ locW, const float* __restrict__ fpW,
                        const float* __restrict__ globW, float* __restrict__ wt,
                        int* __restrict__ deg, int* __restrict__ gdeg) {
    int i = blockIdx.x * blockDim.x + threadIdx.x;
    if (i < 32768)       wt[i] = __uint_as_float(f2tf32(locW[i]));
    else if (i < 50048)  wt[i] = __uint_as_float(f2tf32(fpW[i - 32768]));
    else if (i < WT_TOT) wt[i] = __uint_as_float(f2tf32(globW[i - 50048]));
    if (i < TN)    deg[i]  = 0;
    if (i < NNODE) gdeg[i] = 0;
}

// ================= CSR construction (both graphs fused) =================
__global__ void hist2_k(const int* __restrict__ ldst, const int* __restrict__ gdst,
                        int* __restrict__ deg, int* __restrict__ gdeg) {
    int e = blockIdx.x * blockDim.x + threadIdx.x;
    if (e < ELN) atomicAdd(&deg[ldst[e]], 1);
    else if (e < ELN + EGN) atomicAdd(&gdeg[gdst[e - ELN]], 1);
}
__global__ void scan1b_k(const int* __restrict__ deg, const int* __restrict__ gdeg,
                         int* __restrict__ bsum, int* __restrict__ gbsum) {
    __shared__ int s[256];
    int t = threadIdx.x;
    bool loc = blockIdx.x < NBL;
    const int* d = loc ? deg : gdeg;
    int n = loc ? TN : NNODE;
    int base = (loc ? blockIdx.x : blockIdx.x - NBL) * 1024;
    int sum = 0;
#pragma unroll
    for (int i = 0; i < 4; i++) {
        int idx = base + t * 4 + i;
        if (idx < n) sum += d[idx];
    }
    s[t] = sum; __syncthreads();
    for (int o = 128; o > 0; o >>= 1) { if (t < o) s[t] += s[t + o]; __syncthreads(); }
    if (t == 0) (loc ? bsum : gbsum)[loc ? blockIdx.x : blockIdx.x - NBL] = s[0];
}
__global__ void scan2b_k(int* __restrict__ bsum, int* __restrict__ gbsum,
                         int* __restrict__ rowptr, int* __restrict__ growptr) {
    if (threadIdx.x == 0) {
        int acc = 0;
        for (int i = 0; i < NBL; i++) { int v = bsum[i]; bsum[i] = acc; acc += v; }
        rowptr[TN] = ELN;
    } else if (threadIdx.x == 1) {
        int acc = 0;
        for (int i = 0; i < NBG; i++) { int v = gbsum[i]; gbsum[i] = acc; acc += v; }
        growptr[NNODE] = EGN;
    }
}
__global__ void scan3b_k(const int* __restrict__ deg, const int* __restrict__ gdeg,
                         const int* __restrict__ bsum, const int* __restrict__ gbsum,
                         int* __restrict__ rowptr, int* __restrict__ growptr,
                         int* __restrict__ fill, int* __restrict__ gfill) {
    __shared__ int s[256];
    int t = threadIdx.x;
    bool loc = blockIdx.x < NBL;
    const int* d = loc ? deg : gdeg;
    const int* bs = loc ? bsum : gbsum;
    int* rp = loc ? rowptr : growptr;
    int* fl = loc ? fill : gfill;
    int n = loc ? TN : NNODE;
    int bid = loc ? blockIdx.x : blockIdx.x - NBL;
    int base = bid * 1024;
    int v[4]; int sum = 0;
#pragma unroll
    for (int i = 0; i < 4; i++) {
        int idx = base + t * 4 + i;
        v[i] = (idx < n) ? d[idx] : 0;
        sum += v[i];
    }
    s[t] = sum; __syncthreads();
    for (int o = 1; o < 256; o <<= 1) {
        int x = (t >= o) ? s[t - o] : 0;
        __syncthreads();
        s[t] += x;
        __syncthreads();
    }
    int excl = ((t == 0) ? 0 : s[t - 1]) + bs[bid];
#pragma unroll
    for (int i = 0; i < 4; i++) {
        int idx = base + t * 4 + i;
        if (idx < n) { rp[idx] = excl; fl[idx] = excl; }
        excl += v[i];
    }
}
__global__ void scatedge2_k(const int* __restrict__ lsrc, const int* __restrict__ ldst,
                            const int* __restrict__ gsrc, const int* __restrict__ gdst,
                            const float* __restrict__ eattr,
                            int* __restrict__ fill, int* __restrict__ gfill,
                            int* __restrict__ psrc, float* __restrict__ pea,
                            int* __restrict__ gpsrc) {
    int e = blockIdx.x * blockDim.x + threadIdx.x;
    if (e < ELN) {
        int p = atomicAdd(&fill[ldst[e]], 1);
        psrc[p] = lsrc[e];
        pea[p] = eattr[e];
    } else if (e < ELN + EGN) {
        int ee = e - ELN;
        int p = atomicAdd(&gfill[gdst[ee]], 1);
        gpsrc[p] = gsrc[ee];
    }
}

// ================= tf32 MMA GEMM: BM=128, BK=32, 2-stage cp.async ===============
// IP: input-projection prologue (h = x@Win+bin -> hout, fence, A=hout from L2).
// LNS: epilogue LayerNorm+ReLU, scattered to gx[cid[row]] (no C store).
#define APAD 36
#define WPAD 136
#define ABUF (128 * APAD)
#define WBUF (32 * WPAD)
#define SMEM_MMA ((2 * ABUF + 2 * WBUF) * 4)   // 71680 bytes
template <int NH, bool IP, bool LNS>
__global__ __launch_bounds__(256, 2)
void gemm_mma(const float* __restrict__ A, const float* __restrict__ W,
              const float* __restrict__ bias, float* __restrict__ C,
              int M, int K, int lda,
              const float* __restrict__ asrc, const float* __restrict__ adst,
              float* __restrict__ ssrc, float* __restrict__ sdst,
              const float* __restrict__ x, const float* __restrict__ Win,
              const float* __restrict__ binp, float* __restrict__ hout,
              const float* __restrict__ gamma, const float* __restrict__ beta,
              const int* __restrict__ cidp, float* __restrict__ gxout) {
    extern __shared__ __align__(16) float smem[];
    float* As = smem;
    float* Ws = smem + 2 * ABUF;
    const int tid  = threadIdx.x;
    const int warp = tid >> 5, lane = tid & 31;
    const int bm   = blockIdx.x * 128;
    const int wm   = (warp >> 1) * 32;
    const int wn   = (warp & 1) * 64;
    const int g    = lane >> 2;
    const int ct   = lane & 3;
    const int nk   = (K + 31) / 32;

    if (IP) {
        float* xs   = As;        // 512 floats
        float* WinS = Ws;        // 512 floats
        float* binS = Ws + 512;  // 128 floats
        for (int i = tid; i < 512; i += 256) {
            int m = i >> 2, j = i & 3;
            int gr = bm + m;
            xs[i] = (gr < M) ? x[(size_t)gr * 4 + j] : 0.f;
            WinS[i] = Win[i];
        }
        if (tid < 128) binS[tid] = binp[tid];
        __syncthreads();
        for (int i = tid; i < 128 * 128; i += 256) {
            int m = i >> 7, k = i & 127;
            float v = binS[k]
                    + xs[m * 4 + 0] * WinS[k]
                    + xs[m * 4 + 1] * WinS[128 + k]
                    + xs[m * 4 + 2] * WinS[256 + k]
                    + xs[m * 4 + 3] * WinS[384 + k];
            int gr = bm + m;
            if (gr < M) hout[(size_t)gr * 128 + k] = v;
        }
        __threadfence();
        __syncthreads();
    }

    const unsigned asb = (unsigned)__cvta_generic_to_shared(As);
    const unsigned wsb = (unsigned)__cvta_generic_to_shared(Ws);

    float c[2][8][4];
#pragma unroll
    for (int mt = 0; mt < 2; mt++)
#pragma unroll
        for (int nt = 0; nt < 8; nt++)
#pragma unroll
            for (int r = 0; r < 4; r++) c[mt][nt][r] = 0.f;

    auto issue = [&](int buf, int t) {
        int k0 = t * 32;
#pragma unroll
        for (int j = 0; j < 4; j++) {
            int id = tid + 256 * j;
            int m = id >> 3, kq = (id & 7) * 4;
            int gr = bm + m, gk = k0 + kq;
            int bytes = 0;
            const float* src = A;
            if (gr < M && gk < K) {
                int rem = K - gk;
                bytes = rem >= 4 ? 16 : rem * 4;
                src = A + (size_t)gr * lda + gk;
            }
            cp_async16(asb + (unsigned)(buf * ABUF + m * APAD + kq) * 4u, src, bytes);
        }
#pragma unroll
        for (int j = 0; j < 4; j++) {
            int id = tid + 256 * j;
            int k = id >> 5, nq = (id & 31) * 4;
            int gk = k0 + k;
            int bytes = (gk < K) ? 16 : 0;
            const float* src = (gk < K) ? (W + (size_t)gk * 128 + nq) : W;
            cp_async16(wsb + (unsigned)(buf * WBUF + k * WPAD + nq) * 4u, src, bytes);
        }
        cp_commit();
    };

    issue(0, 0);

    for (int t = 0; t < nk; t++) {
        cp_wait0();
        __syncthreads();
        if (t + 1 < nk) issue((t + 1) & 1, t + 1);

        const float* Ab = As + (t & 1) * ABUF;
        const unsigned* Wb = (const unsigned*)(Ws + (t & 1) * WBUF);
#pragma unroll
        for (int ks = 0; ks < 32; ks += 8) {
            unsigned b[8][2];
#pragma unroll
            for (int nt = 0; nt < 8; nt++) {
                int n = wn + nt * 8 + g;
                b[nt][0] = Wb[(ks + ct) * WPAD + n];
                b[nt][1] = Wb[(ks + ct + 4) * WPAD + n];
            }
#pragma unroll
            for (int mt = 0; mt < 2; mt++) {
                int r0 = wm + mt * 16 + g;
                unsigned a0 = f2tf32(Ab[r0 * APAD + ks + ct]);
                unsigned a1 = f2tf32(Ab[(r0 + 8) * APAD + ks + ct]);
                unsigned a2 = f2tf32(Ab[r0 * APAD + ks + ct + 4]);
                unsigned a3 = f2tf32(Ab[(r0 + 8) * APAD + ks + ct + 4]);
#pragma unroll
                for (int nt = 0; nt < 8; nt++) {
                    asm volatile(
                        "mma.sync.aligned.m16n8k8.row.col.f32.tf32.tf32.f32 "
                        "{%0,%1,%2,%3}, {%4,%5,%6,%7}, {%8,%9}, {%0,%1,%2,%3};"
                        : "+f"(c[mt][nt][0]), "+f"(c[mt][nt][1]),
                          "+f"(c[mt][nt][2]), "+f"(c[mt][nt][3])
                        : "r"(a0), "r"(a1), "r"(a2), "r"(a3),
                          "r"(b[nt][0]), "r"(b[nt][1]));
                }
            }
        }
        __syncthreads();
    }

    if (LNS) {
        // stage tile (+bias) in smem, then per-row LN + ReLU scattered to gx[cid]
        float* T = smem;   // 128 x 132
#pragma unroll
        for (int mt = 0; mt < 2; mt++) {
            int r0 = wm + mt * 16 + g;
            int r1 = r0 + 8;
#pragma unroll
            for (int nt = 0; nt < 8; nt++) {
                int col = wn + nt * 8 + 2 * ct;
                float b0 = bias[col], b1 = bias[col + 1];
                T[r0 * 132 + col]     = c[mt][nt][0] + b0;
                T[r0 * 132 + col + 1] = c[mt][nt][1] + b1;
                T[r1 * 132 + col]     = c[mt][nt][2] + b0;
                T[r1 * 132 + col + 1] = c[mt][nt][3] + b1;
            }
        }
        __syncthreads();
        int r = tid >> 1, half = tid & 1;
        const float* row = T + r * 132 + half * 64;
        float sum = 0.f;
#pragma unroll
        for (int j = 0; j < 64; j++) sum += row[j];
        sum += __shfl_xor_sync(0xffffffffu, sum, 1);
        float mean = sum * (1.f / 128.f);
        float sq = 0.f;
#pragma unroll
        for (int j = 0; j < 64; j++) { float d = row[j] - mean; sq += d * d; }
        sq += __shfl_xor_sync(0xffffffffu, sq, 1);
        float rstd = rsqrtf(sq * (1.f / 128.f) + 1e-5f);
        int grow = bm + r;
        if (grow < M) {
            float* dst = gxout + (size_t)cidp[grow] * 128 + half * 64;
#pragma unroll
            for (int j = 0; j < 64; j++) {
                float y = (row[j] - mean) * rstd * gamma[half * 64 + j] + beta[half * 64 + j];
                dst[j] = fmaxf(y, 0.f);
            }
        }
        return;
    }

    // epilogue: store C (+bias) and optionally fused attention scores
    const int NH2 = (NH == 4) ? 2 : 1;
    float ps[2][2][2], pd[2][2][2];
    if (NH > 0) {
#pragma unroll
        for (int a = 0; a < 2; a++)
#pragma unroll
            for (int b2 = 0; b2 < 2; b2++)
#pragma unroll
                for (int d = 0; d < 2; d++) { ps[a][b2][d] = 0.f; pd[a][b2][d] = 0.f; }
    }
#pragma unroll
    for (int mt = 0; mt < 2; mt++) {
        int row0 = bm + wm + mt * 16 + g;
        int row1 = row0 + 8;
#pragma unroll
        for (int nt = 0; nt < 8; nt++) {
            int col = wn + nt * 8 + 2 * ct;
            float b0 = bias ? bias[col] : 0.f;
            float b1 = bias ? bias[col + 1] : 0.f;
            float v00 = c[mt][nt][0] + b0, v01 = c[mt][nt][1] + b1;
            float v10 = c[mt][nt][2] + b0, v11 = c[mt][nt][3] + b1;
            if (row0 < M) *(float2*)(C + (size_t)row0 * 128 + col) = make_float2(v00, v01);
            if (row1 < M) *(float2*)(C + (size_t)row1 * 128 + col) = make_float2(v10, v11);
            if (NH > 0) {
                float a0s = asrc[col], a1s = asrc[col + 1];
                float a0d = adst[col], a1d = adst[col + 1];
                int h2 = (NH == 4) ? (nt >> 2) : 0;
                ps[mt][0][h2] += v00 * a0s + v01 * a1s;
                ps[mt][1][h2] += v10 * a0s + v11 * a1s;
                pd[mt][0][h2] += v00 * a0d + v01 * a1d;
                pd[mt][1][h2] += v10 * a0d + v11 * a1d;
            }
        }
    }
    if (NH > 0) {
#pragma unroll
        for (int mt = 0; mt < 2; mt++)
#pragma unroll
            for (int rh = 0; rh < 2; rh++)
#pragma unroll
                for (int h2 = 0; h2 < NH2; h2++) {
                    float s = ps[mt][rh][h2], d = pd[mt][rh][h2];
                    s += __shfl_xor_sync(0xffffffffu, s, 1);
                    s += __shfl_xor_sync(0xffffffffu, s, 2);
                    d += __shfl_xor_sync(0xffffffffu, d, 1);
                    d += __shfl_xor_sync(0xffffffffu, d, 2);
                    ps[mt][rh][h2] = s; pd[mt][rh][h2] = d;
                }
        if (ct == 0) {
            int headbase = (wn * NH) >> 7;
#pragma unroll
            for (int mt = 0; mt < 2; mt++)
#pragma unroll
                for (int rh = 0; rh < 2; rh++) {
                    int row = bm + wm + mt * 16 + g + rh * 8;
                    if (row < M) {
#pragma unroll
                        for (int h2 = 0; h2 < NH2; h2++) {
                            int head = headbase + h2;
                            ssrc[(size_t)row * NH + head] = ps[mt][rh][h2];
                            sdst[(size_t)row * NH + head] = pd[mt][rh][h2];
                        }
                    }
                }
        }
    }
}

// ---------------- SIMT GEMM for tiny-K projections (+optional fused LN+ReLU) --------
__global__ __launch_bounds__(256, 2)
void gemm_tile(const float* __restrict__ A, const float* __restrict__ W,
               const float* __restrict__ bias, float* __restrict__ C,
               int M, int K,
               const float* __restrict__ gamma, const float* __restrict__ beta) {
    __shared__ float As[16 * 132];
    __shared__ float Ws[16 * 132];
    const int bm  = blockIdx.x * 128;
    const int tid = threadIdx.x;
    const int tr  = (tid >> 4) * 8;
    const int tc  = (tid & 15) * 8;
    float acc[8][8];
#pragma unroll
    for (int x = 0; x < 8; x++)
#pragma unroll
        for (int y = 0; y < 8; y++) acc[x][y] = 0.f;

    for (int k0 = 0; k0 < K; k0 += 16) {
        for (int i = tid; i < 128 * 16; i += 256) {
            int m = i >> 4, kk = i & 15;
            int gr = bm + m, gk = k0 + kk;
            As[kk * 132 + m] = (gr < M && gk < K) ? A[(size_t)gr * K + gk] : 0.f;
        }
        for (int i = tid; i < 16 * 128; i += 256) {
            int kk = i >> 7, n = i & 127;
            int gk = k0 + kk;
            Ws[kk * 132 + n] = (gk < K) ? W[gk * 128 + n] : 0.f;
        }
        __syncthreads();
#pragma unroll
        for (int kk = 0; kk < 16; kk++) {
            float a[8], w[8];
#pragma unroll
            for (int x = 0; x < 8; x++) a[x] = As[kk * 132 + tr + x];
#pragma unroll
            for (int y = 0; y < 8; y++) w[y] = Ws[kk * 132 + tc + y];
#pragma unroll
            for (int x = 0; x < 8; x++)
#pragma unroll
                for (int y = 0; y < 8; y++) acc[x][y] += a[x] * w[y];
        }
        __syncthreads();
    }

    if (gamma) {
#pragma unroll
        for (int x = 0; x < 8; x++) {
            int gr = bm + tr + x;
            float vv[8]; float sum = 0.f;
#pragma unroll
            for (int y = 0; y < 8; y++) {
                vv[y] = acc[x][y] + (bias ? bias[tc + y] : 0.f);
                sum += vv[y];
            }
#pragma unroll
            for (int k = 1; k < 16; k <<= 1) sum += __shfl_xor_sync(0xffffffffu, sum, k, 16);
            float mean = sum * (1.f / 128.f);
            float sq = 0.f;
#pragma unroll
            for (int y = 0; y < 8; y++) { float d = vv[y] - mean; sq += d * d; }
#pragma unroll
            for (int k = 1; k < 16; k <<= 1) sq += __shfl_xor_sync(0xffffffffu, sq, k, 16);
            float rstd = rsqrtf(sq * (1.f / 128.f) + 1e-5f);
            if (gr < M) {
#pragma unroll
                for (int y = 0; y < 8; y++) {
                    float yv = (vv[y] - mean) * rstd * gamma[tc + y] + beta[tc + y];
                    C[(size_t)gr * 128 + tc + y] = fmaxf(yv, 0.f);
                }
            }
        }
    } else {
#pragma unroll
        for (int x = 0; x < 8; x++) {
            int gr = bm + tr + x;
            if (gr < M) {
#pragma unroll
                for (int y = 0; y < 8; y++) {
                    float v = acc[x][y];
                    if (bias) v += bias[tc + y];
                    C[(size_t)gr * 128 + tc + y] = v;
                }
            }
        }
    }
}

// ---------------- fused single-pass GAT aggregation ----------------
template <int NH, int HD, bool HAS_E>
__global__ void gat_fused(const int* __restrict__ rowptr, const int* __restrict__ psrc,
                          const float* __restrict__ pea,
                          const float* __restrict__ eW, const float* __restrict__ ae,
                          const float* __restrict__ ssrc, const float* __restrict__ sdst,
                          const float* __restrict__ z, const float* __restrict__ bias,
                          float* __restrict__ h, int n) {
    __shared__ float ce_s[NH];
    if (HAS_E && threadIdx.x < NH) {
        int hh = threadIdx.x;
        float s = 0.f;
#pragma unroll
        for (int d = 0; d < HD; d++) s += eW[hh * HD + d] * ae[hh * HD + d];
        ce_s[hh] = s;
    }
    if (HAS_E) __syncthreads();

    int node = blockIdx.x * 8 + (threadIdx.x >> 5);
    if (node >= n) return;
    int lane = threadIdx.x & 31;
    int c = lane * 4;
    int head = c / HD;

    float sd = sdst[(size_t)node * NH + head];
    float ce = HAS_E ? ce_s[head] : 0.f;

    float4 acc = make_float4(0.f, 0.f, 0.f, 0.f);
    float den = 0.f;
    int lo = rowptr[node], hi = rowptr[node + 1];
    for (int j = lo; j < hi; j++) {
        int s = psrc[j];
        float sc = ssrc[(size_t)s * NH + head] + sd;
        if (HAS_E) sc += pea[j] * ce;
        sc = sc > 0.f ? sc : 0.2f * sc;
        float ex = __expf(sc);
        den += ex;
        float4 zv = *(const float4*)(z + (size_t)s * HH + c);
        acc.x += ex * zv.x; acc.y += ex * zv.y;
        acc.z += ex * zv.z; acc.w += ex * zv.w;
    }
    float inv = 1.f / fmaxf(den, 1e-16f);
    float4 hv = *(const float4*)(h + (size_t)node * HH + c);
    float4 bv = *(const float4*)(bias + c);
    acc.x = hv.x + bv.x + acc.x * inv;
    acc.y = hv.y + bv.y + acc.y * inv;
    acc.z = hv.z + bv.z + acc.z * inv;
    acc.w = hv.w + bv.w + acc.w * inv;
    acc.x = acc.x > 0.f ? acc.x : __expf(acc.x) - 1.f;
    acc.y = acc.y > 0.f ? acc.y : __expf(acc.y) - 1.f;
    acc.z = acc.z > 0.f ? acc.z : __expf(acc.z) - 1.f;
    acc.w = acc.w > 0.f ? acc.w : __expf(acc.w) - 1.f;
    *(float4*)(h + (size_t)node * HH + c) = acc;
}

// ---------------- pooling -> padded cat rows (+ gfeat tail) ----------------
__global__ void pool_cat_k(const float* __restrict__ h, const int* __restrict__ nb,
                           const float* __restrict__ gf, const int* __restrict__ cid,
                           float* __restrict__ cat) {
    int b = blockIdx.x, t = threadIdx.x;
    int lo = 0, hi = TN;
    while (lo < hi) { int mid = (lo + hi) >> 1; if (nb[mid] < b) lo = mid + 1; else hi = mid; }
    int start = lo;
    hi = TN;
    while (lo < hi) { int mid = (lo + hi) >> 1; if (nb[mid] < b + 1) lo = mid + 1; else hi = mid; }
    int end = lo;
    float s = 0.f;
    for (int i = start; i < end; i++) s += h[(size_t)i * HH + t];
    cat[(size_t)b * CATP + t] = s / fmaxf((float)(end - start), 1.f);
    if (t < FGN)
        cat[(size_t)b * CATP + HH + t] = gf[(size_t)cid[b] * FGN + t];
}

// ---------------- classifier: 8 contracts per block ----------------
__global__ __launch_bounds__(256)
void classifier_k(const float* __restrict__ gx, const int* __restrict__ cid,
                  const float* __restrict__ W1, const float* __restrict__ b1,
                  const float* __restrict__ W2, const float* __restrict__ b2,
                  float* __restrict__ out) {
    __shared__ float row[4][HH];
    __shared__ float hc[4][HCN];
    int tid = threadIdx.x;
    int grp = tid >> 6, t = tid & 63;
    for (int it = 0; it < 2; it++) {
        int b = blockIdx.x * 8 + it * 4 + grp;
        __syncthreads();
        const float* srcp = gx + (size_t)cid[b] * HH;
        row[grp][t] = srcp[t];
        row[grp][t + 64] = srcp[t + 64];
        __syncthreads();
        float s = b1[t];
#pragma unroll
        for (int k = 0; k < HH; k++) s += row[grp][k] * W1[k * HCN + t];
        hc[grp][t] = fmaxf(s, 0.f);
        __syncthreads();
        if (t < CC) {
            float s2 = b2[t];
#pragma unroll
            for (int k = 0; k < HCN; k++) s2 += hc[grp][k] * W2[k * CC + t];
            out[b * CC + t] = s2;
        }
    }
}

// ---------------- launch ----------------
extern "C" void kernel_launch(void* const* d_in, const int* in_sizes, int n_in,
                              void* d_out, int out_size) {
    const float* x_local    = (const float*)d_in[0];
    const float* eattr      = (const float*)d_in[1];
    const float* gfeat      = (const float*)d_in[2];
    const float* loc_in_W   = (const float*)d_in[3];
    const float* loc_in_b   = (const float*)d_in[4];
    const float* loc_W      = (const float*)d_in[5];
    const float* loc_asrc   = (const float*)d_in[6];
    const float* loc_adst   = (const float*)d_in[7];
    const float* loc_eW     = (const float*)d_in[8];
    const float* loc_ae     = (const float*)d_in[9];
    const float* loc_b      = (const float*)d_in[10];
    const float* fp_W       = (const float*)d_in[11];
    const float* fp_b       = (const float*)d_in[12];
    const float* fp_g       = (const float*)d_in[13];
    const float* fp_beta    = (const float*)d_in[14];
    const float* gp_W       = (const float*)d_in[15];
    const float* gp_b       = (const float*)d_in[16];
    const float* gp_g       = (const float*)d_in[17];
    const float* gp_beta    = (const float*)d_in[18];
    const float* glob_W     = (const float*)d_in[19];
    const float* glob_asrc  = (const float*)d_in[20];
    const float* glob_adst  = (const float*)d_in[21];
    const float* glob_b     = (const float*)d_in[22];
    const float* cls_W1     = (const float*)d_in[23];
    const float* cls_b1     = (const float*)d_in[24];
    const float* cls_W2     = (const float*)d_in[25];
    const float* cls_b2     = (const float*)d_in[26];
    const int*   eil        = (const int*)d_in[27];
    const int*   node_batch = (const int*)d_in[28];
    const int*   cid        = (const int*)d_in[29];
    const int*   gei        = (const int*)d_in[30];

    const int* lsrc = eil;
    const int* ldst = eil + ELN;
    const int* gsrc = gei;
    const int* gdst = gei + EGN;

    float *p_h, *p_z, *p_ssrc, *p_sdst;
    float *p_cat, *p_gx, *p_gz, *p_pea, *p_wtf;
    int *p_deg, *p_rowptr, *p_fill, *p_psrc, *p_bsum;
    int *p_gdeg, *p_growptr, *p_gfill, *p_gpsrc, *p_gbsum;
    cudaGetSymbolAddress((void**)&p_h, g_h);
    cudaGetSymbolAddress((void**)&p_z, g_z);
    cudaGetSymbolAddress((void**)&p_ssrc, g_ssrc);
    cudaGetSymbolAddress((void**)&p_sdst, g_sdst);
    cudaGetSymbolAddress((void**)&p_cat, g_cat);
    cudaGetSymbolAddress((void**)&p_gx, g_gx);
    cudaGetSymbolAddress((void**)&p_gz, g_gz);
    cudaGetSymbolAddress((void**)&p_pea, g_pea);
    cudaGetSymbolAddress((void**)&p_wtf, g_wtf);
    cudaGetSymbolAddress((void**)&p_deg, g_deg);
    cudaGetSymbolAddress((void**)&p_rowptr, g_rowptr);
    cudaGetSymbolAddress((void**)&p_fill, g_fill);
    cudaGetSymbolAddress((void**)&p_psrc, g_psrc);
    cudaGetSymbolAddress((void**)&p_bsum, g_bsum);
    cudaGetSymbolAddress((void**)&p_gdeg, g_gdeg);
    cudaGetSymbolAddress((void**)&p_growptr, g_growptr);
    cudaGetSymbolAddress((void**)&p_gfill, g_gfill);
    cudaGetSymbolAddress((void**)&p_gpsrc, g_gpsrc);
    cudaGetSymbolAddress((void**)&p_gbsum, g_gbsum);

    // dynamic smem opt-in
    cudaFuncSetAttribute((const void*)gemm_mma<4, true, false>,
                         cudaFuncAttributeMaxDynamicSharedMemorySize, SMEM_MMA);
    cudaFuncSetAttribute((const void*)gemm_mma<4, false, false>,
                         cudaFuncAttributeMaxDynamicSharedMemorySize, SMEM_MMA);
    cudaFuncSetAttribute((const void*)gemm_mma<2, false, false>,
                         cudaFuncAttributeMaxDynamicSharedMemorySize, SMEM_MMA);
    cudaFuncSetAttribute((const void*)gemm_mma<0, false, true>,
                         cudaFuncAttributeMaxDynamicSharedMemorySize, SMEM_MMA);

    // ---- weight pre-rounding + deg zeroing ----
    wconv_k<<<CDIV(TN, 256), 256>>>(loc_W, fp_W, glob_W, p_wtf, p_deg, p_gdeg);

    // ---- CSR hist (both graphs) ----
    hist2_k<<<CDIV(ELN + EGN, 256), 256>>>(ldst, gdst, p_deg, p_gdeg);
    scan1b_k<<<NBL + NBG, 256>>>(p_deg, p_gdeg, p_bsum, p_gbsum);

    // ---- local layer 0: fused IP + GEMM (+scores) — ncu slot #4 ----
    gemm_mma<4, true, false><<<CDIV(TN, 128), 256, SMEM_MMA>>>(
        p_h, p_wtf + WT_LOC0, nullptr, p_z, TN, HH, HH,
        loc_asrc, loc_adst, p_ssrc, p_sdst,
        x_local, loc_in_W, loc_in_b, p_h,
        nullptr, nullptr, nullptr, nullptr);

    scan2b_k<<<1, 32>>>(p_bsum, p_gbsum, p_rowptr, p_growptr);
    scan3b_k<<<NBL + NBG, 256>>>(p_deg, p_gdeg, p_bsum, p_gbsum,
                                 p_rowptr, p_growptr, p_fill, p_gfill);
    scatedge2_k<<<CDIV(ELN + EGN, 256), 256>>>(lsrc, ldst, gsrc, gdst, eattr,
                                               p_fill, p_gfill, p_psrc, p_pea, p_gpsrc);

    // ---- local layer 0 aggregate ----
    gat_fused<4, 32, true><<<CDIV(TN, 8), 256>>>(p_rowptr, p_psrc, p_pea,
                                                 loc_eW, loc_ae,
                                                 p_ssrc, p_sdst, p_z, loc_b, p_h, TN);
    // ---- local layer 1 ----
    gemm_mma<4, false, false><<<CDIV(TN, 128), 256, SMEM_MMA>>>(
        p_h, p_wtf + WT_LOC1, nullptr, p_z, TN, HH, HH,
        loc_asrc + HH, loc_adst + HH, p_ssrc, p_sdst,
        nullptr, nullptr, nullptr, nullptr,
        nullptr, nullptr, nullptr, nullptr);
    gat_fused<4, 32, true><<<CDIV(TN, 8), 256>>>(p_rowptr, p_psrc, p_pea,
                                                 loc_eW + HH, loc_ae + HH,
                                                 p_ssrc, p_sdst, p_z, loc_b + HH, p_h, TN);

    // ---- pooling straight into padded cat rows ----
    pool_cat_k<<<BB, 128>>>(p_h, node_batch, gfeat, cid, p_cat);

    // ---- global projection for ALL N (fused LN+ReLU) FIRST ----
    gemm_tile<<<CDIV(NNODE, 128), 256>>>(gfeat, gp_W, gp_b, p_gx, NNODE, FGN,
                                         gp_g, gp_beta);

    // ---- fused MLP with LN+ReLU+scatter epilogue (overwrites gx[cid]) ----
    gemm_mma<0, false, true><<<CDIV(BB, 128), 256, SMEM_MMA>>>(
        p_cat, p_wtf + WT_FP, fp_b, nullptr, BB, HH + FGN, CATP,
        nullptr, nullptr, nullptr, nullptr,
        nullptr, nullptr, nullptr, nullptr,
        fp_g, fp_beta, cid, p_gx);

    // ---- 2x global GATConv ----
    for (int l = 0; l < 2; l++) {
        gemm_mma<2, false, false><<<CDIV(NNODE, 128), 256, SMEM_MMA>>>(
            p_gx, p_wtf + (l == 0 ? WT_G0 : WT_G1), nullptr,
            p_gz, NNODE, HH, HH,
            glob_asrc + l * HH, glob_adst + l * HH, p_ssrc, p_sdst,
            nullptr, nullptr, nullptr, nullptr,
            nullptr, nullptr, nullptr, nullptr);
        gat_fused<2, 64, false><<<CDIV(NNODE, 8), 256>>>(p_growptr, p_gpsrc, (float*)nullptr,
                                                         (float*)nullptr, (float*)nullptr,
                                                         p_ssrc, p_sdst, p_gz,
                                                         glob_b + l * HH, p_gx, NNODE);
    }

    // ---- classifier ----
    classifier_k<<<CDIV(BB, 8), 256>>>(p_gx, cid, cls_W1, cls_b1, cls_W2, cls_b2,
                                       (float*)d_out);
}